// round 16
// baseline (speedup 1.0000x reference)
#include <cuda_runtime.h>
#include <cuda_bf16.h>
#include <math.h>

// Problem constants
#define Bsz     2
#define Npts    8192
#define Kn      3
#define NQ      (Bsz * Npts)
#define THREADS 128
#define WARPS   (THREADS / 32)     // 4 warps per block
#define G       4                  // queries per warp
#define QPB     (WARPS * G)        // 16 queries per block -> 1024 blocks
#define TILE_C  1024               // candidates per smem tile
#define NTILES  (Npts / TILE_C)    // 8 tiles

#define FULLMASK 0xffffffffu

// Precomputed candidate vectors {-2x, -2y, -2z, |s|^2}
__device__ float4 g_c4[NQ];

// Top-3 insert, strict < in ascending candidate order (= top_k tie-break).
// Rechecks f < t2, so stale ballot bits self-filter.
__device__ __forceinline__ void insert3(float f, int cand,
                                        float& t0, float& t1, float& t2,
                                        int& i0, int& i1, int& i2)
{
    if (f < t2) {
        if (f < t0)      { t2 = t1; i2 = i1; t1 = t0; i1 = i0; t0 = f; i0 = cand; }
        else if (f < t1) { t2 = t1; i2 = i1; t1 = f;  i1 = cand; }
        else             { t2 = f;  i2 = cand; }
    }
}

// Prep: build g_c4 and zero the output accumulator.
__global__ void prep_kernel(const float* __restrict__ xyz, float* __restrict__ out)
{
    const int t = blockIdx.x * blockDim.x + threadIdx.x;
    if (t == 0) out[0] = 0.0f;
    if (t >= NQ) return;
    const float x = xyz[t * 3 + 0];
    const float y = xyz[t * 3 + 1];
    const float z = xyz[t * 3 + 2];
    const float n = fmaf(x, x, fmaf(y, y, z * z));
    g_c4[t] = make_float4(-2.0f * x, -2.0f * y, -2.0f * z, n);
}

// Ballot-gated insert of a 32-candidate window for one query.
__device__ __forceinline__ void process_window(float tg, int cbase,
                                               float& t0, float& t1, float& t2,
                                               int& i0, int& i1, int& i2)
{
    unsigned bg = __ballot_sync(FULLMASK, tg < t2);
    while (bg) {
        const int l = __ffs(bg) - 1;
        bg &= bg - 1;
        const float tv = __shfl_sync(FULLMASK, tg, l);
        insert3(tv, cbase + l, t0, t1, t2, i0, i1, i2);
    }
}

// ---------------------------------------------------------------------------
// Fused KNN + loss (R14 structure + double-buffered staging). Warp owns G=4
// queries; lanes process 64 distinct candidates per step (2 float4 loads).
// t-space: t = (-2s).q + |s|^2 = d - |q|^2, monotone per query.
// Tiles are double-buffered: next tile's LDG/STS issue BEFORE scanning the
// current buffer, one barrier per tile (staging latency hides under scan).
// Slow path: per-query ballots over lo then hi window (ascending candidate
// order; insert3 rechecks) -> exact sequential strict-< semantics.
// ---------------------------------------------------------------------------
__global__ __launch_bounds__(THREADS) void knnreg_kernel(
    const float* __restrict__ xyz,   // [B,N,3]
    const float* __restrict__ rot,   // [B,N,4]
    const float* __restrict__ scl,   // [B,N,3]
    const float* __restrict__ col,   // [B,N,45]
    const float* __restrict__ opa,   // [B,N,1]
    float* __restrict__ out)
{
    const int tid  = threadIdx.x;
    const int lane = tid & 31;
    const int wid  = tid >> 5;
    const int qblk = blockIdx.x * QPB;
    const int b    = qblk >> 13;                 // QPB=16 | 8192
    const float* xb = xyz + (size_t)b * Npts * 3;
    const float4* cb4 = g_c4 + (size_t)b * Npts;
    const int qw   = (qblk & (Npts - 1)) + wid * G;

    // Warp's queries (broadcast loads)
    float qx[G], qy[G], qz[G], qn[G];
    #pragma unroll
    for (int g = 0; g < G; g++) {
        const int q = qw + g;
        qx[g] = xb[q * 3 + 0];
        qy[g] = xb[q * 3 + 1];
        qz[g] = xb[q * 3 + 2];
        qn[g] = fmaf(qx[g], qx[g], fmaf(qy[g], qy[g], qz[g] * qz[g]));
    }

    float t0[G], t1[G], t2[G];
    int   i0[G], i1[G], i2[G];

    __shared__ float4 sc[2][TILE_C];
    __shared__ float  red[WARPS];

    // ---- stage tile 0 into buffer 0 ----
    for (int k = tid; k < TILE_C; k += THREADS)
        sc[0][k] = cb4[k];
    __syncthreads();

    // ---- prologue: candidates 0..31 via warp lex-argmin (exact) ----
    {
        const float4 c = sc[0][lane];
        #pragma unroll
        for (int g = 0; g < G; g++) {
            float t = fmaf(qx[g], c.x, c.w);
            t = fmaf(qy[g], c.y, t);
            t = fmaf(qz[g], c.z, t);
            float v = t; int iv = lane;
            float rt[Kn]; int ri[Kn];
            #pragma unroll
            for (int r = 0; r < Kn; r++) {
                float bv = v; int bi = iv;
                #pragma unroll
                for (int off = 16; off > 0; off >>= 1) {
                    const float ov = __shfl_xor_sync(FULLMASK, bv, off);
                    const int   oo = __shfl_xor_sync(FULLMASK, bi, off);
                    if (ov < bv || (ov == bv && oo < bi)) { bv = ov; bi = oo; }
                }
                rt[r] = bv; ri[r] = bi;
                if (iv == bi) v = INFINITY;
            }
            t0[g] = rt[0]; t1[g] = rt[1]; t2[g] = rt[2];
            i0[g] = ri[0]; i1[g] = ri[1]; i2[g] = ri[2];
        }
    }

    // ---- candidates 32..63 (single-width step, aligns main loop to 64) ----
    {
        const float4 c = sc[0][32 + lane];
        float tg[G];
        #pragma unroll
        for (int g = 0; g < G; g++) {
            float t = fmaf(qx[g], c.x, c.w);
            t = fmaf(qy[g], c.y, t);
            tg[g] = fmaf(qz[g], c.z, t);
        }
        const bool p = (tg[0] < t2[0]) | (tg[1] < t2[1])
                     | (tg[2] < t2[2]) | (tg[3] < t2[3]);
        if (__ballot_sync(FULLMASK, p)) {
            #pragma unroll
            for (int g = 0; g < G; g++)
                process_window(tg[g], 32, t0[g], t1[g], t2[g], i0[g], i1[g], i2[g]);
        }
    }

    // ---- main scan: 64 candidates per step, double-buffered tiles ----
    for (int tile = 0; tile < NTILES; tile++) {
        const int buf = tile & 1;

        // Stage NEXT tile into the other buffer (scanned-out last iteration;
        // end-of-iteration barrier makes the overwrite safe). LDG latency
        // overlaps the scan below.
        if (tile + 1 < NTILES) {
            const int nbase = (tile + 1) * TILE_C;
            for (int k = tid; k < TILE_C; k += THREADS)
                sc[buf ^ 1][k] = cb4[nbase + k];
        }

        const int sbeg  = (tile == 0) ? 64 : 0;
        const int tbase = tile * TILE_C;
        for (int s = sbeg; s < TILE_C; s += 64) {
            const float4 ca = sc[buf][s + lane];
            const float4 cb = sc[buf][s + 32 + lane];
            float ta[G], tb[G];
            #pragma unroll
            for (int g = 0; g < G; g++) {
                float t = fmaf(qx[g], ca.x, ca.w);
                t = fmaf(qy[g], ca.y, t);
                ta[g] = fmaf(qz[g], ca.z, t);
                float u = fmaf(qx[g], cb.x, cb.w);
                u = fmaf(qy[g], cb.y, u);
                tb[g] = fmaf(qz[g], cb.z, u);
            }
            const bool p = (ta[0] < t2[0]) | (ta[1] < t2[1])
                         | (ta[2] < t2[2]) | (ta[3] < t2[3])
                         | (tb[0] < t2[0]) | (tb[1] < t2[1])
                         | (tb[2] < t2[2]) | (tb[3] < t2[3]);
            if (__ballot_sync(FULLMASK, p)) {
                const int cbd = tbase + s;
                #pragma unroll
                for (int g = 0; g < G; g++) {
                    // lo window first, then hi: ascending candidate order
                    process_window(ta[g], cbd,      t0[g], t1[g], t2[g], i0[g], i1[g], i2[g]);
                    process_window(tb[g], cbd + 32, t0[g], t1[g], t2[g], i0[g], i1[g], i2[g]);
                }
            }
        }

        // Single barrier per tile: staging of tile+1 complete AND all warps
        // done scanning this buffer before it is overwritten next iteration.
        __syncthreads();
    }

    // ---- fused loss phase ----
    float local = 0.0f;

    #pragma unroll
    for (int g = 0; g < G; g++) {
        if (lane == 0) {
            local += ((t0[g] + qn[g]) + (t1[g] + qn[g]) + (t2[g] + qn[g]))
                     * (1.0f / ((float)Bsz * Npts * Kn));
        }

        const int r0 = b * Npts + i0[g];
        const int r1 = b * Npts + i1[g];
        const int r2 = b * Npts + i2[g];

        // 53 channels: 0..3 rot(4), 4..6 scales(3), 7 opacity(1), 8..52 colors(45)
        for (int c = lane; c < 53; c += 32) {
            const float* bp; int C; int cc;
            if (c < 4)       { bp = rot; C = 4;  cc = c;     }
            else if (c < 7)  { bp = scl; C = 3;  cc = c - 4; }
            else if (c < 8)  { bp = opa; C = 1;  cc = 0;     }
            else             { bp = col; C = 45; cc = c - 8; }

            const float x0 = __ldg(bp + (size_t)r0 * C + cc);
            const float x1 = __ldg(bp + (size_t)r1 * C + cc);
            const float x2 = __ldg(bp + (size_t)r2 * C + cc);

            const float m  = (x0 + x1 + x2) * (1.0f / 3.0f);
            const float e0 = x0 - m, e1 = x1 - m, e2 = x2 - m;
            const float var = fmaf(e0, e0, fmaf(e1, e1, e2 * e2)) * 0.5f; // ddof=1
            local += sqrtf(var) * (1.0f / ((float)Bsz * Npts * (float)C));
        }
    }

    // warp reduce
    #pragma unroll
    for (int off = 16; off > 0; off >>= 1)
        local += __shfl_xor_sync(FULLMASK, local, off);

    if (lane == 0) red[wid] = local;
    __syncthreads();

    if (tid == 0) {
        float s = 0.0f;
        #pragma unroll
        for (int w = 0; w < WARPS; w++) s += red[w];
        atomicAdd(out, s);
    }
}

// ---------------------------------------------------------------------------
extern "C" void kernel_launch(void* const* d_in, const int* in_sizes, int n_in,
                              void* d_out, int out_size)
{
    const float* xyz = (const float*)d_in[0];
    const float* rot = (const float*)d_in[1];
    const float* scl = (const float*)d_in[2];
    const float* col = (const float*)d_in[3];
    const float* opa = (const float*)d_in[4];
    float* out = (float*)d_out;

    prep_kernel<<<NQ / 256, 256>>>(xyz, out);
    knnreg_kernel<<<NQ / QPB, THREADS>>>(xyz, rot, scl, col, opa, out);
}